// round 1
// baseline (speedup 1.0000x reference)
#include <cuda_runtime.h>
#include <math.h>

#define NN 512
#define HC 64

// ---- scratch (device globals; no allocation allowed) ----
__device__ float g_h[NN * 16];
__device__ float g_hi[NN * HC];        // hi_term[i][c] = h[i]@W1_hi[c] + b[i]*w_bi[c]
__device__ float g_hj[NN * HC];        // hj_term[j][c] = h[j]@W1_hj[c] + b[j]*w_bj[c] + b1[c]
__device__ float g_ysum_part[16 * NN * HC];  // 16 deterministic partials of sum_i relu(W2 u + b2)
__device__ float g_mj[NN * 32];

// ---- f32x2 packed helpers ----
__device__ __forceinline__ unsigned long long pk2(float lo, float hi) {
    unsigned long long r;
    asm("mov.b64 %0, {%1, %2};" : "=l"(r) : "f"(lo), "f"(hi));
    return r;
}
__device__ __forceinline__ void fma2(unsigned long long& d, unsigned long long a, unsigned long long b) {
    asm("fma.rn.f32x2 %0, %1, %2, %0;" : "+l"(d) : "l"(a), "l"(b));
}
__device__ __forceinline__ float2 upk2(unsigned long long v) {
    float2 f;
    asm("mov.b64 {%0, %1}, %2;" : "=f"(f.x), "=f"(f.y) : "l"(v));
    return f;
}
__device__ __forceinline__ float sigmoidf(float x) { return 1.0f / (1.0f + expf(-x)); }

// ============================================================
// Init: h0 = 0; hi/hj terms for h=0
// grid 128, block 256  (512*64 threads)
// ============================================================
__global__ void init_kernel(const float* __restrict__ b, const float* __restrict__ W1,
                            const float* __restrict__ b1) {
    int idx = blockIdx.x * 256 + threadIdx.x;   // 0..32767
    int node = idx >> 6, c = idx & 63;
    g_hi[idx] = b[node] * W1[c * 35 + 33];
    g_hj[idx] = fmaf(b[node], W1[c * 35 + 34], b1[c]);
    if (c < 16) g_h[node * 16 + c] = 0.0f;
}

// ============================================================
// Edge kernel: for each edge (i,j):
//   u = relu(hi[i] + hj[j] + J[i,j]*wJ)      (64-d)
//   v = relu(W2 @ u + b2)                    (64-d)
//   ysum_part[j] += v   (summed over this block's i-range)
// grid (32 j-tiles, 8 i-chunks), block 256
// ============================================================
__global__ __launch_bounds__(256, 2) void edge_kernel(const float* __restrict__ J,
                                                      const float* __restrict__ W1,
                                                      const float* __restrict__ W2,
                                                      const float* __restrict__ b2) {
    __shared__ __align__(16) float sW2T[64][64];   // [k][c]
    __shared__ float sU[64][64];                   // [k][e], e = ii*16 + jj
    __shared__ float sHj[16][64];
    __shared__ float sHi[4][64];
    __shared__ float sJ[4][16];
    __shared__ float swJ[64];
    __shared__ float sB2[64];

    const int t = threadIdx.x;
    const int jt = blockIdx.x, ic = blockIdx.y;
    const int j0 = jt * 16;

    // stage W2^T (once)
#pragma unroll
    for (int q = 0; q < 16; q++) {
        int idx = t + q * 256;
        int c = idx >> 6, k = idx & 63;
        sW2T[k][c] = W2[c * 64 + k];
    }
    if (t < 64) { swJ[t] = W1[t * 35 + 32]; sB2[t] = b2[t]; }
#pragma unroll
    for (int q = 0; q < 4; q++) {
        int idx = t + q * 256;
        int jl = idx >> 6, k = idx & 63;
        sHj[jl][k] = g_hj[(j0 + jl) * 64 + k];
    }

    const int cg = t & 7;            // c-group: 8 channels
    const int jj = (t >> 3) & 15;    // j within tile
    const int ig = t >> 7;           // 0/1: which i-pair
    const int e0 = (2 * ig) * 16 + jj;
    const int e1 = e0 + 16;

    // U-build mapping
    const int ue = t & 63;
    const int uii = ue >> 4, ujj = ue & 15;
    const int ukr = t >> 6;          // k-base = ukr*16

    float ysum[8];
#pragma unroll
    for (int q = 0; q < 8; q++) ysum[q] = 0.0f;

    for (int it = 0; it < 16; it++) {
        __syncthreads();
        const int i0 = ic * 64 + it * 4;
        { int ii = t >> 6, k = t & 63; sHi[ii][k] = g_hi[(i0 + ii) * 64 + k]; }
        if (t < 64) sJ[t >> 4][t & 15] = J[(i0 + (t >> 4)) * NN + j0 + (t & 15)];
        __syncthreads();

        // build U tile
        {
            float Jv = sJ[uii][ujj];
#pragma unroll
            for (int kk = 0; kk < 16; kk++) {
                int k = ukr * 16 + kk;
                float u = fmaf(Jv, swJ[k], sHi[uii][k] + sHj[ujj][k]);
                sU[k][ue] = fmaxf(u, 0.0f);
            }
        }
        __syncthreads();

        // GEMM: 2 edges x 8 channels, packed f32x2
        unsigned long long acc0[4] = {0ull, 0ull, 0ull, 0ull};
        unsigned long long acc1[4] = {0ull, 0ull, 0ull, 0ull};
#pragma unroll
        for (int k = 0; k < 64; k++) {
            float a0 = sU[k][e0], a1 = sU[k][e1];
            unsigned long long pa0 = pk2(a0, a0);
            unsigned long long pa1 = pk2(a1, a1);
            const ulonglong2* wp = reinterpret_cast<const ulonglong2*>(&sW2T[k][cg * 8]);
            ulonglong2 w01 = wp[0];
            ulonglong2 w23 = wp[1];
            fma2(acc0[0], pa0, w01.x); fma2(acc0[1], pa0, w01.y);
            fma2(acc0[2], pa0, w23.x); fma2(acc0[3], pa0, w23.y);
            fma2(acc1[0], pa1, w01.x); fma2(acc1[1], pa1, w01.y);
            fma2(acc1[2], pa1, w23.x); fma2(acc1[3], pa1, w23.y);
        }
        // epilogue: bias + relu + accumulate over the 2 i's
#pragma unroll
        for (int p = 0; p < 4; p++) {
            float2 v0 = upk2(acc0[p]);
            float2 v1 = upk2(acc1[p]);
            float bl = sB2[cg * 8 + 2 * p], bh = sB2[cg * 8 + 2 * p + 1];
            ysum[2 * p]     += fmaxf(v0.x + bl, 0.0f) + fmaxf(v1.x + bl, 0.0f);
            ysum[2 * p + 1] += fmaxf(v0.y + bh, 0.0f) + fmaxf(v1.y + bh, 0.0f);
        }
    }

    // deterministic partial write (part = ic*2 + ig, unique per thread)
    const int part = ic * 2 + ig;
    float* dst = &g_ysum_part[(part * NN + (j0 + jj)) * 64 + cg * 8];
#pragma unroll
    for (int q = 0; q < 8; q++) dst[q] = ysum[q];
}

// ============================================================
// m_j: reduce 16 partials, then m_j = Ysum @ W3^T + 512*b3
// grid 64, block 256  (8 j per block)
// ============================================================
__global__ void mj_kernel(const float* __restrict__ W3, const float* __restrict__ b3) {
    __shared__ float sY[8][64];
    const int t = threadIdx.x;
    const int j0 = blockIdx.x * 8;
#pragma unroll
    for (int q = 0; q < 2; q++) {
        int idx = t + q * 256;
        int jl = idx >> 6, k = idx & 63;
        float s = 0.0f;
#pragma unroll
        for (int p = 0; p < 16; p++) s += g_ysum_part[(p * NN + j0 + jl) * 64 + k];
        sY[jl][k] = s;
    }
    __syncthreads();
    const int jl = t >> 5, c2 = t & 31;
    float s = 512.0f * b3[c2];
#pragma unroll
    for (int k = 0; k < 64; k++) s = fmaf(W3[c2 * 64 + k], sY[jl][k], s);
    g_mj[(j0 + jl) * 32 + c2] = s;
}

// ============================================================
// GRU update + recompute hi/hj for next step
// grid 64, block 128 (8 nodes per block)
// ============================================================
__global__ void gru_kernel(const float* __restrict__ W_ih, const float* __restrict__ b_ih,
                           const float* __restrict__ W_hh, const float* __restrict__ b_hh,
                           const float* __restrict__ W1, const float* __restrict__ b1,
                           const float* __restrict__ bn) {
    __shared__ float sH[8][16], sMJ[8][32], sGI[8][48], sGH[8][48], sHn[8][16];
    const int t = threadIdx.x;
    const int n0 = blockIdx.x * 8;

    { int nl = t >> 4, s = t & 15; sH[nl][s] = g_h[(n0 + nl) * 16 + s]; }
#pragma unroll
    for (int q = 0; q < 2; q++) {
        int idx = t + q * 128;
        int nl = idx >> 5, c = idx & 31;
        sMJ[nl][c] = g_mj[(n0 + nl) * 32 + c];
    }
    __syncthreads();

    // gi, gh: 8 nodes x 48 gates
#pragma unroll
    for (int q = 0; q < 3; q++) {
        int idx = t + q * 128;
        int nl = idx / 48, g = idx % 48;
        float gi = b_ih[g], gh = b_hh[g];
#pragma unroll
        for (int s = 0; s < 16; s++) {
            gi = fmaf(sH[nl][s], W_ih[g * 48 + s], gi);
            gh = fmaf(sH[nl][s], W_hh[g * 16 + s], gh);
        }
#pragma unroll
        for (int m = 0; m < 32; m++) gi = fmaf(sMJ[nl][m], W_ih[g * 48 + 16 + m], gi);
        sGI[nl][g] = gi;
        sGH[nl][g] = gh;
    }
    __syncthreads();

    {
        int nl = t >> 4, s = t & 15;
        float r = sigmoidf(sGI[nl][s] + sGH[nl][s]);
        float z = sigmoidf(sGI[nl][16 + s] + sGH[nl][16 + s]);
        float nv = tanhf(sGI[nl][32 + s] + r * sGH[nl][32 + s]);
        float hn = (1.0f - z) * nv + z * sH[nl][s];
        sHn[nl][s] = hn;
        g_h[(n0 + nl) * 16 + s] = hn;
    }
    __syncthreads();

    // hi/hj terms for next step: 8 nodes x 64 c x {hi,hj}
#pragma unroll
    for (int q = 0; q < 8; q++) {
        int idx = t + q * 128;          // 0..1023
        int nl = idx >> 7, rem = idx & 127;
        int c = rem & 63, which = rem >> 6;
        int ng = n0 + nl;
        const float* w = &W1[c * 35 + (which ? 16 : 0)];
        float s = which ? fmaf(bn[ng], W1[c * 35 + 34], b1[c]) : bn[ng] * W1[c * 35 + 33];
#pragma unroll
        for (int sd = 0; sd < 16; sd++) s = fmaf(sHn[nl][sd], w[sd], s);
        if (which) g_hj[ng * 64 + c] = s;
        else       g_hi[ng * 64 + c] = s;
    }
}

// ============================================================
// Readout: relu(h@Wr1^T) -> relu(@Wr2^T) -> sigmoid(@Wr3^T) -> normalize
// grid 256, block 128 (2 nodes per block)
// ============================================================
__global__ void readout_kernel(const float* __restrict__ Wr1, const float* __restrict__ br1,
                               const float* __restrict__ Wr2, const float* __restrict__ br2,
                               const float* __restrict__ Wr3, const float* __restrict__ br3,
                               float* __restrict__ out) {
    __shared__ float sH[2][16], sY1[2][64], sY2[2][64], sY3[2][2];
    const int t = threadIdx.x;
    const int n0 = blockIdx.x * 2;

    if (t < 32) sH[t >> 4][t & 15] = g_h[n0 * 16 + t];
    __syncthreads();

    const int nl = t >> 6, o = t & 63;
    float s = br1[o];
#pragma unroll
    for (int k = 0; k < 16; k++) s = fmaf(sH[nl][k], Wr1[o * 16 + k], s);
    sY1[nl][o] = fmaxf(s, 0.0f);
    __syncthreads();

    s = br2[o];
#pragma unroll
    for (int k = 0; k < 64; k++) s = fmaf(sY1[nl][k], Wr2[o * 64 + k], s);
    sY2[nl][o] = fmaxf(s, 0.0f);
    __syncthreads();

    if (o < 2) {
        s = br3[o];
#pragma unroll
        for (int k = 0; k < 64; k++) s = fmaf(sY2[nl][k], Wr3[o * 64 + k], s);
        sY3[nl][o] = sigmoidf(s);
    }
    __syncthreads();
    if (o < 2) {
        out[(n0 + nl) * 2 + o] = sY3[nl][o] / (sY3[nl][0] + sY3[nl][1]);
    }
}

// ============================================================
extern "C" void kernel_launch(void* const* d_in, const int* in_sizes, int n_in,
                              void* d_out, int out_size) {
    const float* J    = (const float*)d_in[0];
    const float* b    = (const float*)d_in[1];
    const float* W1   = (const float*)d_in[2];
    const float* b1   = (const float*)d_in[3];
    const float* W2   = (const float*)d_in[4];
    const float* b2   = (const float*)d_in[5];
    const float* W3   = (const float*)d_in[6];
    const float* b3   = (const float*)d_in[7];
    const float* W_ih = (const float*)d_in[8];
    const float* b_ih = (const float*)d_in[9];
    const float* W_hh = (const float*)d_in[10];
    const float* b_hh = (const float*)d_in[11];
    const float* Wr1  = (const float*)d_in[12];
    const float* br1  = (const float*)d_in[13];
    const float* Wr2  = (const float*)d_in[14];
    const float* br2  = (const float*)d_in[15];
    const float* Wr3  = (const float*)d_in[16];
    const float* br3  = (const float*)d_in[17];
    float* out = (float*)d_out;

    init_kernel<<<128, 256>>>(b, W1, b1);
    for (int step = 0; step < 5; step++) {
        edge_kernel<<<dim3(32, 8), 256>>>(J, W1, W2, b2);
        mj_kernel<<<64, 256>>>(W3, b3);
        gru_kernel<<<64, 128>>>(W_ih, b_ih, W_hh, b_hh, W1, b1, b);
    }
    readout_kernel<<<256, 128>>>(Wr1, br1, Wr2, br2, Wr3, br3, out);
}

// round 3
// speedup vs baseline: 3.5937x; 3.5937x over previous
#include <cuda_runtime.h>
#include <cstdint>
#include <math.h>

#define NN 512

#if defined(__CUDA_ARCH_FEAT_SM103_ALL) || defined(__CUDA_ARCH_FEAT_SM100_ALL)
#define HAS_TCGEN05 1
#else
#define HAS_TCGEN05 0
#endif

// ---------------- device scratch ----------------
__device__ float g_h[NN * 16];
__device__ float g_hi[NN * 64];
__device__ float g_hj[NN * 64];
__device__ float g_ysum_part[4 * NN * 64];

// ---------------- PTX helpers ----------------
__device__ __forceinline__ uint32_t smem_u32(const void* p) {
    uint32_t a;
    asm("{ .reg .u64 t; cvta.to.shared.u64 t, %1; cvt.u32.u64 %0, t; }" : "=r"(a) : "l"(p));
    return a;
}
__device__ __forceinline__ float tf32_rna(float x) {
    float r;
    asm("cvt.rna.tf32.f32 %0, %1;" : "=f"(r) : "f"(x));
    return r;
}
__device__ __forceinline__ uint32_t sw128(uint32_t b) { return b ^ ((b >> 3) & 0x70); }
__device__ __forceinline__ float sigmoidf(float x) { return 1.0f / (1.0f + expf(-x)); }

#if HAS_TCGEN05
__device__ __forceinline__ uint32_t elect_one() {
    uint32_t p;
    asm volatile("{ .reg .pred p; elect.sync _|p, 0xFFFFFFFF; selp.b32 %0, 1, 0, p; }" : "=r"(p));
    return p;
}
#define MBARRIER_INIT(addr, cnt) \
    asm volatile("mbarrier.init.shared.b64 [%0], %1;" :: "r"((uint32_t)(addr)), "r"((uint32_t)(cnt)) : "memory")
#define MBARRIER_INVAL(addr) \
    asm volatile("mbarrier.inval.shared.b64 [%0];" :: "r"((uint32_t)(addr)) : "memory")
#define MBARRIER_WAIT_PARITY(mbar_smem_addr, phase_parity) do { \
    uint32_t _mbar = (uint32_t)(mbar_smem_addr); \
    uint32_t _parity = (uint32_t)(phase_parity); \
    uint32_t _done; \
    asm volatile( \
        "{\n\t.reg .pred p;\n\t" \
        "mbarrier.try_wait.parity.acquire.cta.shared::cta.b64 p, [%1], %2;\n\t" \
        "selp.b32 %0, 1, 0, p;\n\t}" \
        : "=r"(_done) : "r"(_mbar), "r"(_parity) : "memory"); \
    if (!_done) { \
        asm volatile( \
            "{\n\t.reg .pred P1;\n\t" \
            "WAIT_LOOP_%=:\n\t" \
            "mbarrier.try_wait.parity.acquire.cta.shared::cta.b64 P1, [%0], %1, 0x989680;\n\t" \
            "@P1 bra.uni WAIT_DONE_%=;\n\t" \
            "bra.uni WAIT_LOOP_%=;\n\t" \
            "WAIT_DONE_%=:\n\t}" \
            :: "r"(_mbar), "r"(_parity) : "memory"); \
    } \
} while(0)
#define TCGEN05_ALLOC(saddr, ncols) \
    asm volatile("tcgen05.alloc.cta_group::1.sync.aligned.shared::cta.b32 [%0], %1;" \
                 :: "r"((uint32_t)(saddr)), "r"((uint32_t)(ncols)) : "memory")
#define TCGEN05_DEALLOC(taddr, ncols) \
    asm volatile("tcgen05.dealloc.cta_group::1.sync.aligned.b32 %0, %1;" :: "r"(taddr), "r"((uint32_t)(ncols)))
#define TCGEN05_RELINQ() \
    asm volatile("tcgen05.relinquish_alloc_permit.cta_group::1.sync.aligned;")
#define TCGEN05_COMMIT(mbar) \
    asm volatile("tcgen05.commit.cta_group::1.mbarrier::arrive::one.shared::cluster.b64 [%0];" \
                 :: "r"((uint32_t)(mbar)) : "memory")
#define TCGEN05_FENCE_AFTER()  asm volatile("tcgen05.fence::after_thread_sync;" ::: "memory")
#define TCGEN05_FENCE_BEFORE() asm volatile("tcgen05.fence::before_thread_sync;" ::: "memory")
#define TCGEN05_WAIT_LD()      asm volatile("tcgen05.wait::ld.sync.aligned;" ::: "memory")
#define FENCE_PROXY_ASYNC()    asm volatile("fence.proxy.async.shared::cta;" ::: "memory")

#define TCGEN05_LD_32X32B_X32(r, tmem_addr) \
    asm volatile( \
        "tcgen05.ld.sync.aligned.32x32b.x32.b32 " \
        "{%0, %1, %2, %3, %4, %5, %6, %7, " \
        " %8, %9, %10, %11, %12, %13, %14, %15, " \
        " %16, %17, %18, %19, %20, %21, %22, %23, " \
        " %24, %25, %26, %27, %28, %29, %30, %31}, [%32];" \
        : "=r"((r)[0]),  "=r"((r)[1]),  "=r"((r)[2]),  "=r"((r)[3]), \
          "=r"((r)[4]),  "=r"((r)[5]),  "=r"((r)[6]),  "=r"((r)[7]), \
          "=r"((r)[8]),  "=r"((r)[9]),  "=r"((r)[10]), "=r"((r)[11]), \
          "=r"((r)[12]), "=r"((r)[13]), "=r"((r)[14]), "=r"((r)[15]), \
          "=r"((r)[16]), "=r"((r)[17]), "=r"((r)[18]), "=r"((r)[19]), \
          "=r"((r)[20]), "=r"((r)[21]), "=r"((r)[22]), "=r"((r)[23]), \
          "=r"((r)[24]), "=r"((r)[25]), "=r"((r)[26]), "=r"((r)[27]), \
          "=r"((r)[28]), "=r"((r)[29]), "=r"((r)[30]), "=r"((r)[31]) \
        : "r"(tmem_addr))

// SMEM descriptor: SW128, Blackwell (version=1), SBO=64, LBO=1
static __device__ __forceinline__ uint64_t make_desc(uint32_t addr) {
    const uint64_t base = (uint64_t(2) << 61) | (uint64_t(1) << 46) |
                          (uint64_t(64) << 32) | (uint64_t(1) << 16);
    return base | ((uint64_t)(addr >> 4) & 0x3FFF);
}

// tcgen05.mma kind::tf32, SS, cta_group::1
__device__ __forceinline__ void mma_tf32_ss(uint32_t d, uint64_t ad, uint64_t bd,
                                            uint32_t idesc, bool acc) {
    uint32_t en = acc ? 1u : 0u;
    asm volatile(
        "{\n\t.reg .pred p;\n\t"
        "setp.ne.u32 p, %5, 0;\n\t"
        "tcgen05.mma.cta_group::1.kind::tf32 [%0], %1, %2, %3, {%4, %4, %4, %4}, p;\n\t}"
        :: "r"(d), "l"(ad), "l"(bd), "r"(idesc), "r"(0u), "r"(en) : "memory");
}

// idesc: c=F32(1@[4]), a=TF32(2@[7]), b=TF32(2@[10]), N=64 (8@[17]), M=128 (8@[24])
#define IDESC_TF32 ((1u << 4) | (2u << 7) | (2u << 10) | (8u << 17) | (8u << 24))
#endif  // HAS_TCGEN05

// ---------------- SMEM layout (edge kernel, dynamic) ----------------
#define OFF_UHI   0          // 128x64 f32, swizzled blocked-atom (32768)
#define OFF_ULO   32768
#define OFF_WHI   65536      // 64x64 f32, swizzled (16384)
#define OFF_WLO   81920
#define OFF_HJ    98304      // 16x64 f32 (4096)
#define OFF_HI    102400     // 8x64 f32 (2048)
#define OFF_J     104448     // 8x16 f32 (512)
#define OFF_WJ    104960     // 64 f32
#define OFF_B2    105216     // 64 f32
#define OFF_TPTR  105472
#define OFF_MBAR  105488
#define SMEM_EDGE 105600

// ============================================================
// Init: h0 = 0; hi/hj terms for h=0
// ============================================================
__global__ void init_kernel(const float* __restrict__ b, const float* __restrict__ W1,
                            const float* __restrict__ b1) {
    int idx = blockIdx.x * 256 + threadIdx.x;
    int node = idx >> 6, c = idx & 63;
    g_hi[idx] = b[node] * W1[c * 35 + 33];
    g_hj[idx] = fmaf(b[node], W1[c * 35 + 34], b1[c]);
    if (c < 16) g_h[node * 16 + c] = 0.0f;
}

// ============================================================
// Edge kernel: per block (jt, ic): 16 j's, 128 i's.
//   u = relu(hi[i] + hj[j] + J[i,j]*wJ)   (64)
//   v = relu(W2 @ u + b2)                 (64)
//   ysum_part[ic][j] = sum_i v
// grid (32, 4), block 256
// ============================================================
__global__ __launch_bounds__(256, 1) void edge_tc_kernel(const float* __restrict__ J,
                                                         const float* __restrict__ W1,
                                                         const float* __restrict__ W2,
                                                         const float* __restrict__ b2) {
    extern __shared__ __align__(1024) char smem[];
    const int t = threadIdx.x;
    const int jt = blockIdx.x, ic = blockIdx.y;
    const int j0 = jt * 16;

    float* sHj = (float*)(smem + OFF_HJ);
    float* sHi = (float*)(smem + OFF_HI);
    float* sJ  = (float*)(smem + OFF_J);
    float* swJ = (float*)(smem + OFF_WJ);
    float* sB2 = (float*)(smem + OFF_B2);

#if HAS_TCGEN05
    const uint32_t sbase = smem_u32(smem);
    const int wid = t >> 5, lid = t & 31;

    if (wid == 0) {
        TCGEN05_ALLOC(sbase + OFF_TPTR, 128);
        TCGEN05_RELINQ();
    }
    if (t == 0) MBARRIER_INIT(sbase + OFF_MBAR, 1);

    // stage W2 hi/lo (SW128 blocked atoms: rows=c (64 -> 8 atom-rows), k split in 2 atom-cols)
#pragma unroll
    for (int q = 0; q < 16; q++) {
        int idx = t + q * 256;
        int c = idx >> 6, k = idx & 63;
        float w = W2[c * 64 + k];
        float whi = tf32_rna(w);
        float wlo = w - whi;
        uint32_t byte = (((c >> 3) + ((k >> 5) << 3)) << 10) + ((c & 7) << 7) + ((k & 31) << 2);
        byte = sw128(byte);
        *(float*)(smem + OFF_WHI + byte) = whi;
        *(float*)(smem + OFF_WLO + byte) = wlo;
    }
    if (t < 64) { swJ[t] = W1[t * 35 + 32]; sB2[t] = b2[t]; }
#pragma unroll
    for (int q = 0; q < 4; q++) {
        int idx = t + q * 256;
        sHj[idx] = g_hj[(j0 + (idx >> 6)) * 64 + (idx & 63)];
    }
    FENCE_PROXY_ASYNC();
    __syncthreads();

    const uint32_t tmem = *(volatile uint32_t*)(smem + OFF_TPTR);
    const uint64_t dAhi = make_desc(sbase + OFF_UHI);
    const uint64_t dAlo = make_desc(sbase + OFF_ULO);
    const uint64_t dBhi = make_desc(sbase + OFF_WHI);
    const uint64_t dBlo = make_desc(sbase + OFF_WLO);

    const int chb = (wid >> 2) * 32;     // channel base for this warp
    float b2v[32];
#pragma unroll
    for (int c = 0; c < 32; c++) b2v[c] = sB2[chb + c];

    float ysum[32];
#pragma unroll
    for (int c = 0; c < 32; c++) ysum[c] = 0.0f;

    for (int r = 0; r < 16; r++) {
        const int i0 = ic * 128 + r * 8;
        {
            int idx = t;
            sHi[idx] = g_hi[(i0 + (idx >> 6)) * 64 + (idx & 63)];
            idx = t + 256;
            sHi[idx] = g_hi[(i0 + (idx >> 6)) * 64 + (idx & 63)];
        }
        if (t < 128) sJ[t] = J[(i0 + (t >> 4)) * NN + j0 + (t & 15)];
        __syncthreads();

        // U build: warp wid handles ii = wid, lane handles k = kh*32+lid
        {
            const int ii = wid;
#pragma unroll
            for (int kh = 0; kh < 2; kh++) {
                const int k = kh * 32 + lid;
                const float hiv = sHi[ii * 64 + k];
                const float wJk = swJ[k];
#pragma unroll
                for (int jj = 0; jj < 16; jj++) {
                    const int e = ii * 16 + jj;
                    float u = fmaf(sJ[ii * 16 + jj], wJk, hiv + sHj[jj * 64 + k]);
                    u = fmaxf(u, 0.0f);
                    float uh = tf32_rna(u);
                    float ul = u - uh;
                    uint32_t byte = (((e >> 3) + (kh << 4)) << 10) + ((e & 7) << 7) + (lid << 2);
                    byte = sw128(byte);
                    *(float*)(smem + OFF_UHI + byte) = uh;
                    *(float*)(smem + OFF_ULO + byte) = ul;
                }
            }
        }
        FENCE_PROXY_ASYNC();
        __syncthreads();

        if (wid == 0) {
            if (elect_one()) {
                const uint32_t offA[8] = {0, 2, 4, 6, 1024, 1026, 1028, 1030};
                const uint32_t offB[8] = {0, 2, 4, 6, 512, 514, 516, 518};
#pragma unroll
                for (int s = 0; s < 8; s++)
                    mma_tf32_ss(tmem, dAhi + offA[s], dBhi + offB[s], IDESC_TF32, s > 0);
#pragma unroll
                for (int s = 0; s < 8; s++)
                    mma_tf32_ss(tmem, dAlo + offA[s], dBhi + offB[s], IDESC_TF32, true);
#pragma unroll
                for (int s = 0; s < 8; s++)
                    mma_tf32_ss(tmem, dAhi + offA[s], dBlo + offB[s], IDESC_TF32, true);
                TCGEN05_COMMIT(sbase + OFF_MBAR);
            }
        }
        MBARRIER_WAIT_PARITY(sbase + OFF_MBAR, r & 1);
        TCGEN05_FENCE_AFTER();

        uint32_t tmp[32];
        TCGEN05_LD_32X32B_X32(tmp, tmem + chb);
        TCGEN05_WAIT_LD();
#pragma unroll
        for (int c = 0; c < 32; c++) {
            float v = __uint_as_float(tmp[c]) + b2v[c];
            ysum[c] += fmaxf(v, 0.0f);
        }
        TCGEN05_FENCE_BEFORE();
    }

    // cross-lane reduce over ii (lane l and l^16 share jj) and write partials
    __syncthreads();
    float* sRed = (float*)(smem + OFF_UHI);    // reuse U space: [4 sub][16 jj][64 ch]
    const int sub = wid & 3;
#pragma unroll
    for (int c = 0; c < 32; c++) {
        float v = ysum[c] + __shfl_xor_sync(0xFFFFFFFFu, ysum[c], 16);
        if (lid < 16) sRed[(sub * 16 + lid) * 64 + chb + c] = v;
    }
    __syncthreads();
#pragma unroll
    for (int q = 0; q < 4; q++) {
        int o = t * 4 + q;
        int jj = o >> 6, ch = o & 63;
        float s = sRed[(0 * 16 + jj) * 64 + ch] + sRed[(1 * 16 + jj) * 64 + ch] +
                  sRed[(2 * 16 + jj) * 64 + ch] + sRed[(3 * 16 + jj) * 64 + ch];
        g_ysum_part[(ic * NN + j0 + jj) * 64 + ch] = s;
    }

    __syncthreads();
    if (t == 0) MBARRIER_INVAL(sbase + OFF_MBAR);
    if (wid == 0) TCGEN05_DEALLOC(tmem, 128);

#else  // ---------- scalar fallback (family-PTX pass; never runs on sm_103a) ----------
    float* sW2 = (float*)(smem + OFF_WHI);     // [c][k] linear
    float* sU  = (float*)(smem + OFF_UHI);     // [k][16]

#pragma unroll
    for (int q = 0; q < 16; q++) {
        int idx = t + q * 256;
        sW2[idx] = W2[idx];
    }
    if (t < 64) { swJ[t] = W1[t * 35 + 32]; sB2[t] = b2[t]; }
#pragma unroll
    for (int q = 0; q < 4; q++) {
        int idx = t + q * 256;
        sHj[idx] = g_hj[(j0 + (idx >> 6)) * 64 + (idx & 63)];
    }
    __syncthreads();

    const int jj = t >> 4;
    float acc[4] = {0.f, 0.f, 0.f, 0.f};
    for (int i = ic * 128; i < ic * 128 + 128; i++) {
        if (t < 64) sHi[t] = g_hi[i * 64 + t];
        if (t < 16) sJ[t] = J[i * NN + j0 + t];
        __syncthreads();
#pragma unroll
        for (int q = 0; q < 4; q++) {
            int idx = t * 4 + q;
            int k = idx >> 4, jl = idx & 15;
            float u = fmaf(sJ[jl], swJ[k], sHi[k] + sHj[jl * 64 + k]);
            sU[k * 16 + jl] = fmaxf(u, 0.0f);
        }
        __syncthreads();
#pragma unroll
        for (int q = 0; q < 4; q++) {
            int ch = (t & 15) * 4 + q;
            float v = sB2[ch];
            for (int k = 0; k < 64; k++) v = fmaf(sW2[ch * 64 + k], sU[k * 16 + jj], v);
            acc[q] += fmaxf(v, 0.0f);
        }
        __syncthreads();
    }
#pragma unroll
    for (int q = 0; q < 4; q++) {
        int ch = (t & 15) * 4 + q;
        g_ysum_part[(ic * NN + j0 + jj) * 64 + ch] = acc[q];
    }
#endif
}

// ============================================================
// Fused m_j + GRU + next-step hi/hj
// grid 64, block 256 (8 nodes per block)
// ============================================================
__global__ void mj_gru_kernel(const float* __restrict__ W3, const float* __restrict__ b3,
                              const float* __restrict__ W_ih, const float* __restrict__ b_ih,
                              const float* __restrict__ W_hh, const float* __restrict__ b_hh,
                              const float* __restrict__ W1, const float* __restrict__ b1,
                              const float* __restrict__ bn) {
    __shared__ float sY[8][64];
    __shared__ float sH[8][16], sMJ[8][32], sGI[8][48], sGH[8][48], sHn[8][16];
    const int t = threadIdx.x;
    const int j0 = blockIdx.x * 8;

    // reduce 4 partials
#pragma unroll
    for (int q = 0; q < 2; q++) {
        int idx = t + q * 256;
        int jl = idx >> 6, k = idx & 63;
        float s = 0.0f;
#pragma unroll
        for (int p = 0; p < 4; p++) s += g_ysum_part[(p * NN + j0 + jl) * 64 + k];
        sY[jl][k] = s;
    }
    if (t < 128) { int nl = t >> 4, s = t & 15; sH[nl][s] = g_h[(j0 + nl) * 16 + s]; }
    __syncthreads();

    // m_j: 8 j x 32 ch (exactly 256 threads)
    {
        const int jl = t >> 5, c2 = t & 31;
        float s = 512.0f * b3[c2];
#pragma unroll
        for (int k = 0; k < 64; k++) s = fmaf(W3[c2 * 64 + k], sY[jl][k], s);
        sMJ[jl][c2] = s;
    }
    __syncthreads();

    // gates: 8 nodes x 48
#pragma unroll
    for (int q = 0; q < 2; q++) {
        int idx = t + q * 256;
        if (idx < 384) {
            int nl = idx / 48, g = idx % 48;
            float gi = b_ih[g], gh = b_hh[g];
#pragma unroll
            for (int s = 0; s < 16; s++) {
                gi = fmaf(sH[nl][s], W_ih[g * 48 + s], gi);
                gh = fmaf(sH[nl][s], W_hh[g * 16 + s], gh);
            }
#pragma unroll
            for (int m = 0; m < 32; m++) gi = fmaf(sMJ[nl][m], W_ih[g * 48 + 16 + m], gi);
            sGI[nl][g] = gi;
            sGH[nl][g] = gh;
        }
    }
    __syncthreads();

    if (t < 128) {
        int nl = t >> 4, s = t & 15;
        float r = sigmoidf(sGI[nl][s] + sGH[nl][s]);
        float z = sigmoidf(sGI[nl][16 + s] + sGH[nl][16 + s]);
        float nv = tanhf(sGI[nl][32 + s] + r * sGH[nl][32 + s]);
        float hn = (1.0f - z) * nv + z * sH[nl][s];
        sHn[nl][s] = hn;
        g_h[(j0 + nl) * 16 + s] = hn;
    }
    __syncthreads();

    // hi/hj for next step: 8 nodes x 64 c x {hi,hj} = 1024 outputs
#pragma unroll
    for (int q = 0; q < 4; q++) {
        int idx = t + q * 256;
        int nl = idx >> 7, rem = idx & 127;
        int c = rem & 63, which = rem >> 6;
        int ng = j0 + nl;
        const float* w = &W1[c * 35 + (which ? 16 : 0)];
        float s = which ? fmaf(bn[ng], W1[c * 35 + 34], b1[c]) : bn[ng] * W1[c * 35 + 33];
#pragma unroll
        for (int sd = 0; sd < 16; sd++) s = fmaf(sHn[nl][sd], w[sd], s);
        if (which) g_hj[ng * 64 + c] = s;
        else       g_hi[ng * 64 + c] = s;
    }
}

// ============================================================
// Readout
// ============================================================
__global__ void readout_kernel(const float* __restrict__ Wr1, const float* __restrict__ br1,
                               const float* __restrict__ Wr2, const float* __restrict__ br2,
                               const float* __restrict__ Wr3, const float* __restrict__ br3,
                               float* __restrict__ out) {
    __shared__ float sH[2][16], sY1[2][64], sY2[2][64], sY3[2][2];
    const int t = threadIdx.x;
    const int n0 = blockIdx.x * 2;

    if (t < 32) sH[t >> 4][t & 15] = g_h[n0 * 16 + t];
    __syncthreads();

    const int nl = t >> 6, o = t & 63;
    float s = br1[o];
#pragma unroll
    for (int k = 0; k < 16; k++) s = fmaf(sH[nl][k], Wr1[o * 16 + k], s);
    sY1[nl][o] = fmaxf(s, 0.0f);
    __syncthreads();

    s = br2[o];
#pragma unroll
    for (int k = 0; k < 64; k++) s = fmaf(sY1[nl][k], Wr2[o * 64 + k], s);
    sY2[nl][o] = fmaxf(s, 0.0f);
    __syncthreads();

    if (o < 2) {
        s = br3[o];
#pragma unroll
        for (int k = 0; k < 64; k++) s = fmaf(sY2[nl][k], Wr3[o * 64 + k], s);
        sY3[nl][o] = sigmoidf(s);
    }
    __syncthreads();
    if (o < 2) {
        out[(n0 + nl) * 2 + o] = sY3[nl][o] / (sY3[nl][0] + sY3[nl][1]);
    }
}

// ============================================================
extern "C" void kernel_launch(void* const* d_in, const int* in_sizes, int n_in,
                              void* d_out, int out_size) {
    const float* J    = (const float*)d_in[0];
    const float* b    = (const float*)d_in[1];
    const float* W1   = (const float*)d_in[2];
    const float* b1   = (const float*)d_in[3];
    const float* W2   = (const float*)d_in[4];
    const float* b2   = (const float*)d_in[5];
    const float* W3   = (const float*)d_in[6];
    const float* b3   = (const float*)d_in[7];
    const float* W_ih = (const float*)d_in[8];
    const float* b_ih = (const float*)d_in[9];
    const float* W_hh = (const float*)d_in[10];
    const float* b_hh = (const float*)d_in[11];
    const float* Wr1  = (const float*)d_in[12];
    const float* br1  = (const float*)d_in[13];
    const float* Wr2  = (const float*)d_in[14];
    const float* br2  = (const float*)d_in[15];
    const float* Wr3  = (const float*)d_in[16];
    const float* br3  = (const float*)d_in[17];
    float* out = (float*)d_out;

    cudaFuncSetAttribute(edge_tc_kernel, cudaFuncAttributeMaxDynamicSharedMemorySize, SMEM_EDGE);

    init_kernel<<<128, 256>>>(b, W1, b1);
    for (int step = 0; step < 5; step++) {
        edge_tc_kernel<<<dim3(32, 4), 256, SMEM_EDGE>>>(J, W1, W2, b2);
        mj_gru_kernel<<<64, 256>>>(W3, b3, W_ih, b_ih, W_hh, b_hh, W1, b1, b);
    }
    readout_kernel<<<256, 128>>>(Wr1, br1, Wr2, br2, Wr3, br3, out);
}

// round 4
// speedup vs baseline: 4.4307x; 1.2329x over previous
#include <cuda_runtime.h>
#include <cstdint>
#include <math.h>

#define NN 512

#if defined(__CUDA_ARCH_FEAT_SM103_ALL) || defined(__CUDA_ARCH_FEAT_SM100_ALL)
#define HAS_TCGEN05 1
#else
#define HAS_TCGEN05 0
#endif

// ---------------- device scratch ----------------
__device__ float g_h[NN * 16];
__device__ float g_hi[NN * 64];
__device__ float g_hj[NN * 64];
__device__ float g_ysum_part[4 * NN * 64];

// ---------------- PTX helpers ----------------
__device__ __forceinline__ uint32_t smem_u32(const void* p) {
    uint32_t a;
    asm("{ .reg .u64 t; cvta.to.shared.u64 t, %1; cvt.u32.u64 %0, t; }" : "=r"(a) : "l"(p));
    return a;
}
__device__ __forceinline__ float tf32_rna(float x) {
    float r;
    asm("cvt.rna.tf32.f32 %0, %1;" : "=f"(r) : "f"(x));
    return r;
}
__device__ __forceinline__ uint32_t sw128(uint32_t b) { return b ^ ((b >> 3) & 0x70); }
__device__ __forceinline__ float sigmoidf(float x) { return 1.0f / (1.0f + expf(-x)); }

#if HAS_TCGEN05
__device__ __forceinline__ uint32_t elect_one() {
    uint32_t p;
    asm volatile("{ .reg .pred p; elect.sync _|p, 0xFFFFFFFF; selp.b32 %0, 1, 0, p; }" : "=r"(p));
    return p;
}
#define MBARRIER_INIT(addr, cnt) \
    asm volatile("mbarrier.init.shared.b64 [%0], %1;" :: "r"((uint32_t)(addr)), "r"((uint32_t)(cnt)) : "memory")
#define MBARRIER_INVAL(addr) \
    asm volatile("mbarrier.inval.shared.b64 [%0];" :: "r"((uint32_t)(addr)) : "memory")
#define MBARRIER_WAIT_PARITY(mbar_smem_addr, phase_parity) do { \
    uint32_t _mbar = (uint32_t)(mbar_smem_addr); \
    uint32_t _parity = (uint32_t)(phase_parity); \
    uint32_t _done; \
    asm volatile( \
        "{\n\t.reg .pred p;\n\t" \
        "mbarrier.try_wait.parity.acquire.cta.shared::cta.b64 p, [%1], %2;\n\t" \
        "selp.b32 %0, 1, 0, p;\n\t}" \
        : "=r"(_done) : "r"(_mbar), "r"(_parity) : "memory"); \
    if (!_done) { \
        asm volatile( \
            "{\n\t.reg .pred P1;\n\t" \
            "WAIT_LOOP_%=:\n\t" \
            "mbarrier.try_wait.parity.acquire.cta.shared::cta.b64 P1, [%0], %1, 0x989680;\n\t" \
            "@P1 bra.uni WAIT_DONE_%=;\n\t" \
            "bra.uni WAIT_LOOP_%=;\n\t" \
            "WAIT_DONE_%=:\n\t}" \
            :: "r"(_mbar), "r"(_parity) : "memory"); \
    } \
} while(0)
#define TCGEN05_ALLOC(saddr, ncols) \
    asm volatile("tcgen05.alloc.cta_group::1.sync.aligned.shared::cta.b32 [%0], %1;" \
                 :: "r"((uint32_t)(saddr)), "r"((uint32_t)(ncols)) : "memory")
#define TCGEN05_DEALLOC(taddr, ncols) \
    asm volatile("tcgen05.dealloc.cta_group::1.sync.aligned.b32 %0, %1;" :: "r"(taddr), "r"((uint32_t)(ncols)))
#define TCGEN05_RELINQ() \
    asm volatile("tcgen05.relinquish_alloc_permit.cta_group::1.sync.aligned;")
#define TCGEN05_COMMIT(mbar) \
    asm volatile("tcgen05.commit.cta_group::1.mbarrier::arrive::one.shared::cluster.b64 [%0];" \
                 :: "r"((uint32_t)(mbar)) : "memory")
#define TCGEN05_FENCE_AFTER()  asm volatile("tcgen05.fence::after_thread_sync;" ::: "memory")
#define TCGEN05_FENCE_BEFORE() asm volatile("tcgen05.fence::before_thread_sync;" ::: "memory")
#define TCGEN05_WAIT_LD()      asm volatile("tcgen05.wait::ld.sync.aligned;" ::: "memory")
#define FENCE_PROXY_ASYNC()    asm volatile("fence.proxy.async.shared::cta;" ::: "memory")

#define TCGEN05_LD_32X32B_X32(r, tmem_addr) \
    asm volatile( \
        "tcgen05.ld.sync.aligned.32x32b.x32.b32 " \
        "{%0, %1, %2, %3, %4, %5, %6, %7, " \
        " %8, %9, %10, %11, %12, %13, %14, %15, " \
        " %16, %17, %18, %19, %20, %21, %22, %23, " \
        " %24, %25, %26, %27, %28, %29, %30, %31}, [%32];" \
        : "=r"((r)[0]),  "=r"((r)[1]),  "=r"((r)[2]),  "=r"((r)[3]), \
          "=r"((r)[4]),  "=r"((r)[5]),  "=r"((r)[6]),  "=r"((r)[7]), \
          "=r"((r)[8]),  "=r"((r)[9]),  "=r"((r)[10]), "=r"((r)[11]), \
          "=r"((r)[12]), "=r"((r)[13]), "=r"((r)[14]), "=r"((r)[15]), \
          "=r"((r)[16]), "=r"((r)[17]), "=r"((r)[18]), "=r"((r)[19]), \
          "=r"((r)[20]), "=r"((r)[21]), "=r"((r)[22]), "=r"((r)[23]), \
          "=r"((r)[24]), "=r"((r)[25]), "=r"((r)[26]), "=r"((r)[27]), \
          "=r"((r)[28]), "=r"((r)[29]), "=r"((r)[30]), "=r"((r)[31]) \
        : "r"(tmem_addr))

// SMEM descriptor: SW128, Blackwell (version=1), SBO=64, LBO=1
static __device__ __forceinline__ uint64_t make_desc(uint32_t addr) {
    const uint64_t base = (uint64_t(2) << 61) | (uint64_t(1) << 46) |
                          (uint64_t(64) << 32) | (uint64_t(1) << 16);
    return base | ((uint64_t)(addr >> 4) & 0x3FFF);
}

// tcgen05.mma kind::tf32, SS, cta_group::1
__device__ __forceinline__ void mma_tf32_ss(uint32_t d, uint64_t ad, uint64_t bd,
                                            uint32_t idesc, bool acc) {
    uint32_t en = acc ? 1u : 0u;
    asm volatile(
        "{\n\t.reg .pred p;\n\t"
        "setp.ne.u32 p, %5, 0;\n\t"
        "tcgen05.mma.cta_group::1.kind::tf32 [%0], %1, %2, %3, {%4, %4, %4, %4}, p;\n\t}"
        :: "r"(d), "l"(ad), "l"(bd), "r"(idesc), "r"(0u), "r"(en) : "memory");
}

// idesc: c=F32(1@[4]), a=TF32(2@[7]), b=TF32(2@[10]), N=64 (8@[17]), M=128 (8@[24])
#define IDESC_TF32 ((1u << 4) | (2u << 7) | (2u << 10) | (8u << 17) | (8u << 24))
#endif  // HAS_TCGEN05

// ---------------- SMEM layout (edge kernel, dynamic) ----------------
// Double-buffered U: buf b at b*65536 (hi at +0, lo at +32768)
#define OFF_WHI  131072      // 64x64 f32 swizzled (16384)
#define OFF_WLO  147456
#define OFF_HJ   163840      // 16x64 f32 (4096)
#define OFF_WJ   167936      // 64 f32
#define OFF_B2   168192      // 64 f32
#define OFF_TPTR 168448
#define OFF_MBAR 168464      // 2 mbarriers (+0, +8)
#define SMEM_EDGE 168512
// fallback-only offsets (reuse U buffer space)
#define OFF_FHI  65536
#define OFF_FJ   66560

// ============================================================
// Init: h0 = 0; hi/hj terms for h=0
// ============================================================
__global__ void init_kernel(const float* __restrict__ b, const float* __restrict__ W1,
                            const float* __restrict__ b1) {
    int idx = blockIdx.x * 256 + threadIdx.x;
    int node = idx >> 6, c = idx & 63;
    g_hi[idx] = b[node] * W1[c * 35 + 33];
    g_hj[idx] = fmaf(b[node], W1[c * 35 + 34], b1[c]);
    if (c < 16) g_h[node * 16 + c] = 0.0f;
}

// ============================================================
// Edge kernel: pipelined tcgen05 tf32 (3-pass compensated)
// grid (32 j-tiles, 4 i-chunks), block 256
// ============================================================
__global__ __launch_bounds__(256, 1) void edge_tc_kernel(const float* __restrict__ J,
                                                         const float* __restrict__ W1,
                                                         const float* __restrict__ W2,
                                                         const float* __restrict__ b2) {
    extern __shared__ __align__(1024) char smem[];
    const int t = threadIdx.x;
    const int jt = blockIdx.x, ic = blockIdx.y;
    const int j0 = jt * 16;

    float* sHj = (float*)(smem + OFF_HJ);
    float* swJ = (float*)(smem + OFF_WJ);
    float* sB2 = (float*)(smem + OFF_B2);

#if HAS_TCGEN05
    const uint32_t sbase = smem_u32(smem);
    const int wid = t >> 5, lid = t & 31;

    if (wid == 0) {
        TCGEN05_ALLOC(sbase + OFF_TPTR, 128);
        TCGEN05_RELINQ();
    }
    if (t == 0) { MBARRIER_INIT(sbase + OFF_MBAR, 1); MBARRIER_INIT(sbase + OFF_MBAR + 8, 1); }

    // stage W2 hi/lo (SW128 blocked atoms)
#pragma unroll
    for (int q = 0; q < 16; q++) {
        int idx = t + q * 256;
        int c = idx >> 6, k = idx & 63;
        float w = W2[c * 64 + k];
        float whi = tf32_rna(w);
        float wlo = w - whi;
        uint32_t byte = (((c >> 3) + ((k >> 5) << 3)) << 10) + ((c & 7) << 7) + ((k & 31) << 2);
        byte = sw128(byte);
        *(float*)(smem + OFF_WHI + byte) = whi;
        *(float*)(smem + OFF_WLO + byte) = wlo;
    }
    if (t < 64) { swJ[t] = W1[t * 35 + 32]; sB2[t] = b2[t]; }
#pragma unroll
    for (int q = 0; q < 4; q++) {
        int idx = t + q * 256;
        sHj[idx] = g_hj[(j0 + (idx >> 6)) * 64 + (idx & 63)];
    }
    FENCE_PROXY_ASYNC();
    __syncthreads();

    const uint32_t tmem = *(volatile uint32_t*)(smem + OFF_TPTR);
    const uint64_t dBhi = make_desc(sbase + OFF_WHI);
    const uint64_t dBlo = make_desc(sbase + OFF_WLO);

    const int chb = (wid >> 2) * 32;
    float b2v[32];
#pragma unroll
    for (int c = 0; c < 32; c++) b2v[c] = sB2[chb + c];

    float ysum[32];
#pragma unroll
    for (int c = 0; c < 32; c++) ysum[c] = 0.0f;

    // prefetch round 0 operands (per-warp row i0+wid)
    const int ibase = ic * 128;
    float hp0 = g_hi[(ibase + wid) * 64 + lid];
    float hp1 = g_hi[(ibase + wid) * 64 + 32 + lid];
    float jp  = J[(ibase + wid) * NN + j0 + (lid & 15)];

    const uint32_t offA[8] = {0, 2, 4, 6, 1024, 1026, 1028, 1030};
    const uint32_t offB[8] = {0, 2, 4, 6, 512, 514, 516, 518};

    for (int r = 0; r < 16; r++) {
        const int bank = r & 1;
        char* ubase = smem + bank * 65536;

        // ---- build U[bank] (warp wid owns row ii = wid) ----
#pragma unroll
        for (int kh = 0; kh < 2; kh++) {
            const int k = kh * 32 + lid;
            const float hiv = kh ? hp1 : hp0;
            const float wJk = swJ[k];
#pragma unroll
            for (int jj = 0; jj < 16; jj++) {
                const float Jv = __shfl_sync(0xFFFFFFFFu, jp, jj);
                const int e = wid * 16 + jj;
                float u = fmaf(Jv, wJk, hiv + sHj[jj * 64 + k]);
                u = fmaxf(u, 0.0f);
                float uh = tf32_rna(u);
                float ul = u - uh;
                uint32_t byte = (((e >> 3) + (kh << 4)) << 10) + ((e & 7) << 7) + (lid << 2);
                byte = sw128(byte);
                *(float*)(ubase + byte) = uh;
                *(float*)(ubase + 32768 + byte) = ul;
            }
        }

        // ---- prefetch round r+1 ----
        float hn0 = 0.f, hn1 = 0.f, jn = 0.f;
        if (r < 15) {
            const int i0n = ibase + (r + 1) * 8;
            hn0 = g_hi[(i0n + wid) * 64 + lid];
            hn1 = g_hi[(i0n + wid) * 64 + 32 + lid];
            jn  = J[(i0n + wid) * NN + j0 + (lid & 15)];
        }

        FENCE_PROXY_ASYNC();
        __syncthreads();

        // ---- issue MMA for round r (bank) ----
        if (wid == 0) {
            TCGEN05_FENCE_AFTER();
            if (elect_one()) {
                const uint64_t dAhi = make_desc(sbase + bank * 65536);
                const uint64_t dAlo = make_desc(sbase + bank * 65536 + 32768);
                const uint32_t dst = tmem + bank * 64;
#pragma unroll
                for (int s = 0; s < 8; s++)
                    mma_tf32_ss(dst, dAhi + offA[s], dBhi + offB[s], IDESC_TF32, s > 0);
#pragma unroll
                for (int s = 0; s < 8; s++)
                    mma_tf32_ss(dst, dAlo + offA[s], dBhi + offB[s], IDESC_TF32, true);
#pragma unroll
                for (int s = 0; s < 8; s++)
                    mma_tf32_ss(dst, dAhi + offA[s], dBlo + offB[s], IDESC_TF32, true);
                TCGEN05_COMMIT(sbase + OFF_MBAR + bank * 8);
            }
        }

        // ---- epilogue for round r-1 (other bank), overlapped with MMA r ----
        if (r > 0) {
            const int pb = (r - 1) & 1;
            MBARRIER_WAIT_PARITY(sbase + OFF_MBAR + pb * 8, ((r - 1) >> 1) & 1);
            TCGEN05_FENCE_AFTER();
            uint32_t tmp[32];
            TCGEN05_LD_32X32B_X32(tmp, tmem + pb * 64 + chb);
            TCGEN05_WAIT_LD();
#pragma unroll
            for (int c = 0; c < 32; c++) {
                float v = __uint_as_float(tmp[c]) + b2v[c];
                ysum[c] += fmaxf(v, 0.0f);
            }
            TCGEN05_FENCE_BEFORE();
        }

        hp0 = hn0; hp1 = hn1; jp = jn;
    }

    // ---- tail epilogue (round 15, bank 1) ----
    {
        MBARRIER_WAIT_PARITY(sbase + OFF_MBAR + 8, (15 >> 1) & 1);
        TCGEN05_FENCE_AFTER();
        uint32_t tmp[32];
        TCGEN05_LD_32X32B_X32(tmp, tmem + 64 + chb);
        TCGEN05_WAIT_LD();
#pragma unroll
        for (int c = 0; c < 32; c++) {
            float v = __uint_as_float(tmp[c]) + b2v[c];
            ysum[c] += fmaxf(v, 0.0f);
        }
        TCGEN05_FENCE_BEFORE();
    }

    // cross-lane reduce over ii (lane l and l^16 share jj) and write partials
    __syncthreads();
    float* sRed = (float*)smem;    // reuse U space: [4 sub][16 jj][64 ch]
    const int sub = wid & 3;
#pragma unroll
    for (int c = 0; c < 32; c++) {
        float v = ysum[c] + __shfl_xor_sync(0xFFFFFFFFu, ysum[c], 16);
        if (lid < 16) sRed[(sub * 16 + lid) * 64 + chb + c] = v;
    }
    __syncthreads();
#pragma unroll
    for (int q = 0; q < 4; q++) {
        int o = t * 4 + q;
        int jj = o >> 6, ch = o & 63;
        float s = sRed[(0 * 16 + jj) * 64 + ch] + sRed[(1 * 16 + jj) * 64 + ch] +
                  sRed[(2 * 16 + jj) * 64 + ch] + sRed[(3 * 16 + jj) * 64 + ch];
        g_ysum_part[(ic * NN + j0 + jj) * 64 + ch] = s;
    }

    __syncthreads();
    if (t == 0) { MBARRIER_INVAL(sbase + OFF_MBAR); MBARRIER_INVAL(sbase + OFF_MBAR + 8); }
    if (wid == 0) TCGEN05_DEALLOC(tmem, 128);

#else  // ---------- scalar fallback (family-PTX pass; never runs on sm_103a) ----------
    float* sW2 = (float*)(smem + OFF_WHI);     // [c][k] linear
    float* sU  = (float*)smem;                 // [k][16]
    float* sHi = (float*)(smem + OFF_FHI);
    float* sJ  = (float*)(smem + OFF_FJ);

#pragma unroll
    for (int q = 0; q < 16; q++) {
        int idx = t + q * 256;
        sW2[idx] = W2[idx];
    }
    if (t < 64) { swJ[t] = W1[t * 35 + 32]; sB2[t] = b2[t]; }
#pragma unroll
    for (int q = 0; q < 4; q++) {
        int idx = t + q * 256;
        sHj[idx] = g_hj[(j0 + (idx >> 6)) * 64 + (idx & 63)];
    }
    __syncthreads();

    const int jj = t >> 4;
    float acc[4] = {0.f, 0.f, 0.f, 0.f};
    for (int i = ic * 128; i < ic * 128 + 128; i++) {
        if (t < 64) sHi[t] = g_hi[i * 64 + t];
        if (t < 16) sJ[t] = J[i * NN + j0 + t];
        __syncthreads();
#pragma unroll
        for (int q = 0; q < 4; q++) {
            int idx = t * 4 + q;
            int k = idx >> 4, jl = idx & 15;
            float u = fmaf(sJ[jl], swJ[k], sHi[k] + sHj[jl * 64 + k]);
            sU[k * 16 + jl] = fmaxf(u, 0.0f);
        }
        __syncthreads();
#pragma unroll
        for (int q = 0; q < 4; q++) {
            int ch = (t & 15) * 4 + q;
            float v = sB2[ch];
            for (int k = 0; k < 64; k++) v = fmaf(sW2[ch * 64 + k], sU[k * 16 + jj], v);
            acc[q] += fmaxf(v, 0.0f);
        }
        __syncthreads();
    }
#pragma unroll
    for (int q = 0; q < 4; q++) {
        int ch = (t & 15) * 4 + q;
        g_ysum_part[(ic * NN + j0 + jj) * 64 + ch] = acc[q];
    }
#endif
}

// ============================================================
// Fused m_j + GRU + next-step hi/hj
// grid 128, block 128 (4 nodes per block)
// ============================================================
__global__ void mj_gru_kernel(const float* __restrict__ W3, const float* __restrict__ b3,
                              const float* __restrict__ W_ih, const float* __restrict__ b_ih,
                              const float* __restrict__ W_hh, const float* __restrict__ b_hh,
                              const float* __restrict__ W1, const float* __restrict__ b1,
                              const float* __restrict__ bn) {
    __shared__ float sY[4][64];
    __shared__ float sH[4][16], sMJ[4][32], sGI[4][48], sGH[4][48], sHn[4][16];
    const int t = threadIdx.x;
    const int n0 = blockIdx.x * 4;

    // reduce 4 partials: 4 nodes x 64 ch
#pragma unroll
    for (int q = 0; q < 2; q++) {
        int idx = t + q * 128;
        int jl = idx >> 6, k = idx & 63;
        float s = 0.0f;
#pragma unroll
        for (int p = 0; p < 4; p++) s += g_ysum_part[(p * NN + n0 + jl) * 64 + k];
        sY[jl][k] = s;
    }
    if (t < 64) { int nl = t >> 4, s = t & 15; sH[nl][s] = g_h[(n0 + nl) * 16 + s]; }
    __syncthreads();

    // m_j: 4 nodes x 32 ch = 128 threads
    {
        const int jl = t >> 5, c2 = t & 31;
        float s = 512.0f * b3[c2];
#pragma unroll
        for (int k = 0; k < 64; k++) s = fmaf(W3[c2 * 64 + k], sY[jl][k], s);
        sMJ[jl][c2] = s;
    }
    __syncthreads();

    // gates: 4 nodes x 48 = 192
#pragma unroll
    for (int q = 0; q < 2; q++) {
        int idx = t + q * 128;
        if (idx < 192) {
            int nl = idx / 48, g = idx % 48;
            float gi = b_ih[g], gh = b_hh[g];
#pragma unroll
            for (int s = 0; s < 16; s++) {
                gi = fmaf(sH[nl][s], W_ih[g * 48 + s], gi);
                gh = fmaf(sH[nl][s], W_hh[g * 16 + s], gh);
            }
#pragma unroll
            for (int m = 0; m < 32; m++) gi = fmaf(sMJ[nl][m], W_ih[g * 48 + 16 + m], gi);
            sGI[nl][g] = gi;
            sGH[nl][g] = gh;
        }
    }
    __syncthreads();

    if (t < 64) {
        int nl = t >> 4, s = t & 15;
        float r = sigmoidf(sGI[nl][s] + sGH[nl][s]);
        float z = sigmoidf(sGI[nl][16 + s] + sGH[nl][16 + s]);
        float nv = tanhf(sGI[nl][32 + s] + r * sGH[nl][32 + s]);
        float hn = (1.0f - z) * nv + z * sH[nl][s];
        sHn[nl][s] = hn;
        g_h[(n0 + nl) * 16 + s] = hn;
    }
    __syncthreads();

    // hi/hj for next step: 4 nodes x 64 c x {hi,hj} = 512 outputs
#pragma unroll
    for (int q = 0; q < 4; q++) {
        int idx = t + q * 128;
        int nl = idx >> 7, rem = idx & 127;
        int c = rem & 63, which = rem >> 6;
        int ng = n0 + nl;
        const float* w = &W1[c * 35 + (which ? 16 : 0)];
        float s = which ? fmaf(bn[ng], W1[c * 35 + 34], b1[c]) : bn[ng] * W1[c * 35 + 33];
#pragma unroll
        for (int sd = 0; sd < 16; sd++) s = fmaf(sHn[nl][sd], w[sd], s);
        if (which) g_hj[ng * 64 + c] = s;
        else       g_hi[ng * 64 + c] = s;
    }
}

// ============================================================
// Readout
// ============================================================
__global__ void readout_kernel(const float* __restrict__ Wr1, const float* __restrict__ br1,
                               const float* __restrict__ Wr2, const float* __restrict__ br2,
                               const float* __restrict__ Wr3, const float* __restrict__ br3,
                               float* __restrict__ out) {
    __shared__ float sH[2][16], sY1[2][64], sY2[2][64], sY3[2][2];
    const int t = threadIdx.x;
    const int n0 = blockIdx.x * 2;

    if (t < 32) sH[t >> 4][t & 15] = g_h[n0 * 16 + t];
    __syncthreads();

    const int nl = t >> 6, o = t & 63;
    float s = br1[o];
#pragma unroll
    for (int k = 0; k < 16; k++) s = fmaf(sH[nl][k], Wr1[o * 16 + k], s);
    sY1[nl][o] = fmaxf(s, 0.0f);
    __syncthreads();

    s = br2[o];
#pragma unroll
    for (int k = 0; k < 64; k++) s = fmaf(sY1[nl][k], Wr2[o * 64 + k], s);
    sY2[nl][o] = fmaxf(s, 0.0f);
    __syncthreads();

    if (o < 2) {
        s = br3[o];
#pragma unroll
        for (int k = 0; k < 64; k++) s = fmaf(sY2[nl][k], Wr3[o * 64 + k], s);
        sY3[nl][o] = sigmoidf(s);
    }
    __syncthreads();
    if (o < 2) {
        out[(n0 + nl) * 2 + o] = sY3[nl][o] / (sY3[nl][0] + sY3[nl][1]);
    }
}

// ============================================================
extern "C" void kernel_launch(void* const* d_in, const int* in_sizes, int n_in,
                              void* d_out, int out_size) {
    const float* J    = (const float*)d_in[0];
    const float* b    = (const float*)d_in[1];
    const float* W1   = (const float*)d_in[2];
    const float* b1   = (const float*)d_in[3];
    const float* W2   = (const float*)d_in[4];
    const float* b2   = (const float*)d_in[5];
    const float* W3   = (const float*)d_in[6];
    const float* b3   = (const float*)d_in[7];
    const float* W_ih = (const float*)d_in[8];
    const float* b_ih = (const float*)d_in[9];
    const float* W_hh = (const float*)d_in[10];
    const float* b_hh = (const float*)d_in[11];
    const float* Wr1  = (const float*)d_in[12];
    const float* br1  = (const float*)d_in[13];
    const float* Wr2  = (const float*)d_in[14];
    const float* br2  = (const float*)d_in[15];
    const float* Wr3  = (const float*)d_in[16];
    const float* br3  = (const float*)d_in[17];
    float* out = (float*)d_out;

    cudaFuncSetAttribute(edge_tc_kernel, cudaFuncAttributeMaxDynamicSharedMemorySize, SMEM_EDGE);

    init_kernel<<<128, 256>>>(b, W1, b1);
    for (int step = 0; step < 5; step++) {
        edge_tc_kernel<<<dim3(32, 4), 256, SMEM_EDGE>>>(J, W1, W2, b2);
        mj_gru_kernel<<<128, 128>>>(W3, b3, W_ih, b_ih, W_hh, b_hh, W1, b1, b);
    }
    readout_kernel<<<256, 128>>>(Wr1, br1, Wr2, br2, Wr3, br3, out);
}

// round 5
// speedup vs baseline: 6.2408x; 1.4085x over previous
#include <cuda_runtime.h>
#include <cstdint>
#include <math.h>

#define NN 512

#if defined(__CUDA_ARCH_FEAT_SM103_ALL) || defined(__CUDA_ARCH_FEAT_SM100_ALL)
#define HAS_TCGEN05 1
#else
#define HAS_TCGEN05 0
#endif

// ---------------- device scratch ----------------
__device__ float g_h[NN * 16];
__device__ float g_hi[NN * 64];
__device__ float g_hj[NN * 64];
__device__ float g_ysum_part[8 * NN * 64];

// ---------------- PTX helpers ----------------
__device__ __forceinline__ uint32_t smem_u32(const void* p) {
    uint32_t a;
    asm("{ .reg .u64 t; cvta.to.shared.u64 t, %1; cvt.u32.u64 %0, t; }" : "=r"(a) : "l"(p));
    return a;
}
__device__ __forceinline__ float tf32_rna(float x) {
    float r;
    asm("cvt.rna.tf32.f32 %0, %1;" : "=f"(r) : "f"(x));
    return r;
}
__device__ __forceinline__ uint32_t sw128(uint32_t b) { return b ^ ((b >> 3) & 0x70); }
__device__ __forceinline__ float sigmoidf(float x) { return 1.0f / (1.0f + expf(-x)); }

#if HAS_TCGEN05
__device__ __forceinline__ uint32_t elect_one() {
    uint32_t p;
    asm volatile("{ .reg .pred p; elect.sync _|p, 0xFFFFFFFF; selp.b32 %0, 1, 0, p; }" : "=r"(p));
    return p;
}
#define MBARRIER_INIT(addr, cnt) \
    asm volatile("mbarrier.init.shared.b64 [%0], %1;" :: "r"((uint32_t)(addr)), "r"((uint32_t)(cnt)) : "memory")
#define MBARRIER_INVAL(addr) \
    asm volatile("mbarrier.inval.shared.b64 [%0];" :: "r"((uint32_t)(addr)) : "memory")
#define MBARRIER_WAIT_PARITY(mbar_smem_addr, phase_parity) do { \
    uint32_t _mbar = (uint32_t)(mbar_smem_addr); \
    uint32_t _parity = (uint32_t)(phase_parity); \
    uint32_t _done; \
    asm volatile( \
        "{\n\t.reg .pred p;\n\t" \
        "mbarrier.try_wait.parity.acquire.cta.shared::cta.b64 p, [%1], %2;\n\t" \
        "selp.b32 %0, 1, 0, p;\n\t}" \
        : "=r"(_done) : "r"(_mbar), "r"(_parity) : "memory"); \
    if (!_done) { \
        asm volatile( \
            "{\n\t.reg .pred P1;\n\t" \
            "WAIT_LOOP_%=:\n\t" \
            "mbarrier.try_wait.parity.acquire.cta.shared::cta.b64 P1, [%0], %1, 0x989680;\n\t" \
            "@P1 bra.uni WAIT_DONE_%=;\n\t" \
            "bra.uni WAIT_LOOP_%=;\n\t" \
            "WAIT_DONE_%=:\n\t}" \
            :: "r"(_mbar), "r"(_parity) : "memory"); \
    } \
} while(0)
#define TCGEN05_ALLOC(saddr, ncols) \
    asm volatile("tcgen05.alloc.cta_group::1.sync.aligned.shared::cta.b32 [%0], %1;" \
                 :: "r"((uint32_t)(saddr)), "r"((uint32_t)(ncols)) : "memory")
#define TCGEN05_DEALLOC(taddr, ncols) \
    asm volatile("tcgen05.dealloc.cta_group::1.sync.aligned.b32 %0, %1;" :: "r"(taddr), "r"((uint32_t)(ncols)))
#define TCGEN05_RELINQ() \
    asm volatile("tcgen05.relinquish_alloc_permit.cta_group::1.sync.aligned;")
#define TCGEN05_COMMIT(mbar) \
    asm volatile("tcgen05.commit.cta_group::1.mbarrier::arrive::one.shared::cluster.b64 [%0];" \
                 :: "r"((uint32_t)(mbar)) : "memory")
#define TCGEN05_FENCE_AFTER()  asm volatile("tcgen05.fence::after_thread_sync;" ::: "memory")
#define TCGEN05_FENCE_BEFORE() asm volatile("tcgen05.fence::before_thread_sync;" ::: "memory")
#define TCGEN05_WAIT_LD()      asm volatile("tcgen05.wait::ld.sync.aligned;" ::: "memory")
#define FENCE_PROXY_ASYNC()    asm volatile("fence.proxy.async.shared::cta;" ::: "memory")

#define TCGEN05_LD_32X32B_X32(r, tmem_addr) \
    asm volatile( \
        "tcgen05.ld.sync.aligned.32x32b.x32.b32 " \
        "{%0, %1, %2, %3, %4, %5, %6, %7, " \
        " %8, %9, %10, %11, %12, %13, %14, %15, " \
        " %16, %17, %18, %19, %20, %21, %22, %23, " \
        " %24, %25, %26, %27, %28, %29, %30, %31}, [%32];" \
        : "=r"((r)[0]),  "=r"((r)[1]),  "=r"((r)[2]),  "=r"((r)[3]), \
          "=r"((r)[4]),  "=r"((r)[5]),  "=r"((r)[6]),  "=r"((r)[7]), \
          "=r"((r)[8]),  "=r"((r)[9]),  "=r"((r)[10]), "=r"((r)[11]), \
          "=r"((r)[12]), "=r"((r)[13]), "=r"((r)[14]), "=r"((r)[15]), \
          "=r"((r)[16]), "=r"((r)[17]), "=r"((r)[18]), "=r"((r)[19]), \
          "=r"((r)[20]), "=r"((r)[21]), "=r"((r)[22]), "=r"((r)[23]), \
          "=r"((r)[24]), "=r"((r)[25]), "=r"((r)[26]), "=r"((r)[27]), \
          "=r"((r)[28]), "=r"((r)[29]), "=r"((r)[30]), "=r"((r)[31]) \
        : "r"(tmem_addr))

// SMEM descriptor: SW128, Blackwell (version=1), SBO=64, LBO=1
static __device__ __forceinline__ uint64_t make_desc(uint32_t addr) {
    const uint64_t base = (uint64_t(2) << 61) | (uint64_t(1) << 46) |
                          (uint64_t(64) << 32) | (uint64_t(1) << 16);
    return base | ((uint64_t)(addr >> 4) & 0x3FFF);
}

// tcgen05.mma kind::tf32, SS, cta_group::1
__device__ __forceinline__ void mma_tf32_ss(uint32_t d, uint64_t ad, uint64_t bd,
                                            uint32_t idesc, bool acc) {
    uint32_t en = acc ? 1u : 0u;
    asm volatile(
        "{\n\t.reg .pred p;\n\t"
        "setp.ne.u32 p, %5, 0;\n\t"
        "tcgen05.mma.cta_group::1.kind::tf32 [%0], %1, %2, %3, {%4, %4, %4, %4}, p;\n\t}"
        :: "r"(d), "l"(ad), "l"(bd), "r"(idesc), "r"(0u), "r"(en) : "memory");
}

// idesc: c=F32(1@[4]), a=TF32(2@[7]), b=TF32(2@[10]), N=64 (8@[17]), M=128 (8@[24])
#define IDESC_TF32 ((1u << 4) | (2u << 7) | (2u << 10) | (8u << 17) | (8u << 24))
#endif  // HAS_TCGEN05

// ---------------- SMEM layout (edge kernel, dynamic) ----------------
// Double-buffered U_hi only: bank b at b*32768 (32 KB each)
#define OFF_WHI  65536       // 64x64 f32 swizzled (16384)
#define OFF_WLO  81920
#define OFF_HJ   98304       // 16x64 f32 (4096)
#define OFF_WJ   102400      // 64 f32
#define OFF_B2   102656      // 64 f32
#define OFF_TPTR 102912
#define OFF_MBAR 102928      // 2 mbarriers (+0, +8)
#define SMEM_EDGE 102976
// fallback-only offsets (reuse U buffer space)
#define OFF_FHI  32768
#define OFF_FJ   33792

// ============================================================
// Init: h0 = 0; hi/hj terms for h=0
// ============================================================
__global__ void init_kernel(const float* __restrict__ b, const float* __restrict__ W1,
                            const float* __restrict__ b1) {
    int idx = blockIdx.x * 256 + threadIdx.x;
    int node = idx >> 6, c = idx & 63;
    g_hi[idx] = b[node] * W1[c * 35 + 33];
    g_hj[idx] = fmaf(b[node], W1[c * 35 + 34], b1[c]);
    if (c < 16) g_h[node * 16 + c] = 0.0f;
}

// ============================================================
// Edge kernel: pipelined tcgen05 tf32 (2-pass: Uhi*Whi + Uhi*Wlo)
// grid (32 j-tiles, 8 i-chunks), block 256, 2 CTAs/SM
// ============================================================
__global__ __launch_bounds__(256, 2) void edge_tc_kernel(const float* __restrict__ J,
                                                         const float* __restrict__ W1,
                                                         const float* __restrict__ W2,
                                                         const float* __restrict__ b2) {
    extern __shared__ __align__(1024) char smem[];
    const int t = threadIdx.x;
    const int jt = blockIdx.x, ic = blockIdx.y;
    const int j0 = jt * 16;

    float* sHj = (float*)(smem + OFF_HJ);
    float* swJ = (float*)(smem + OFF_WJ);
    float* sB2 = (float*)(smem + OFF_B2);

#if HAS_TCGEN05
    const uint32_t sbase = smem_u32(smem);
    const int wid = t >> 5, lid = t & 31;

    if (wid == 0) {
        TCGEN05_ALLOC(sbase + OFF_TPTR, 128);
        TCGEN05_RELINQ();
    }
    if (t == 0) { MBARRIER_INIT(sbase + OFF_MBAR, 1); MBARRIER_INIT(sbase + OFF_MBAR + 8, 1); }

    // stage W2 hi/lo (SW128 blocked atoms)
#pragma unroll
    for (int q = 0; q < 16; q++) {
        int idx = t + q * 256;
        int c = idx >> 6, k = idx & 63;
        float w = W2[c * 64 + k];
        float whi = tf32_rna(w);
        float wlo = w - whi;
        uint32_t byte = (((c >> 3) + ((k >> 5) << 3)) << 10) + ((c & 7) << 7) + ((k & 31) << 2);
        byte = sw128(byte);
        *(float*)(smem + OFF_WHI + byte) = whi;
        *(float*)(smem + OFF_WLO + byte) = wlo;
    }
    if (t < 64) { swJ[t] = W1[t * 35 + 32]; sB2[t] = b2[t]; }
#pragma unroll
    for (int q = 0; q < 4; q++) {
        int idx = t + q * 256;
        sHj[idx] = g_hj[(j0 + (idx >> 6)) * 64 + (idx & 63)];
    }
    FENCE_PROXY_ASYNC();
    __syncthreads();

    const uint32_t tmem = *(volatile uint32_t*)(smem + OFF_TPTR);
    const uint64_t dBhi = make_desc(sbase + OFF_WHI);
    const uint64_t dBlo = make_desc(sbase + OFF_WLO);

    const int chb = (wid >> 2) * 32;
    float b2v[32];
#pragma unroll
    for (int c = 0; c < 32; c++) b2v[c] = sB2[chb + c];

    float ysum[32];
#pragma unroll
    for (int c = 0; c < 32; c++) ysum[c] = 0.0f;

    // per-lane fixed k-quad
    const int k0 = (lid & 15) * 4;
    const float4 wq = *(const float4*)&swJ[k0];

    // prefetch round 0 operands (warp owns row i0+wid)
    const int ibase = ic * 64;
    float4 hv = *(const float4*)&g_hi[(ibase + wid) * 64 + k0];
    float jp = J[(ibase + wid) * NN + j0 + (lid & 15)];

    const uint32_t offA[8] = {0, 2, 4, 6, 1024, 1026, 1028, 1030};
    const uint32_t offB[8] = {0, 2, 4, 6, 512, 514, 516, 518};

    // precomputed store base (varies only with jj via e)
    const uint32_t kpart = ((uint32_t)(k0 >> 5) << 14) + ((k0 & 31) << 2);

    for (int r = 0; r < 8; r++) {
        const int bank = r & 1;
        char* ubase = smem + bank * 32768;

        // ---- build U_hi[bank]: 8 iterations, float4 stores ----
#pragma unroll
        for (int m = 0; m < 8; m++) {
            const int jj = 2 * m + (lid >> 4);
            const float Jv = __shfl_sync(0xFFFFFFFFu, jp, jj);
            const float4 hj4 = *(const float4*)&sHj[jj * 64 + k0];
            const int e = wid * 16 + jj;
            float4 u;
            u.x = tf32_rna(fmaxf(fmaf(Jv, wq.x, hv.x + hj4.x), 0.0f));
            u.y = tf32_rna(fmaxf(fmaf(Jv, wq.y, hv.y + hj4.y), 0.0f));
            u.z = tf32_rna(fmaxf(fmaf(Jv, wq.z, hv.z + hj4.z), 0.0f));
            u.w = tf32_rna(fmaxf(fmaf(Jv, wq.w, hv.w + hj4.w), 0.0f));
            uint32_t byte = ((uint32_t)(e >> 3) << 10) + ((e & 7) << 7) + kpart;
            byte = sw128(byte);
            *(float4*)(ubase + byte) = u;
        }

        // ---- prefetch round r+1 ----
        float4 hn = make_float4(0.f, 0.f, 0.f, 0.f);
        float jn = 0.f;
        if (r < 7) {
            const int i0n = ibase + (r + 1) * 8;
            hn = *(const float4*)&g_hi[(i0n + wid) * 64 + k0];
            jn = J[(i0n + wid) * NN + j0 + (lid & 15)];
        }

        FENCE_PROXY_ASYNC();
        __syncthreads();

        // ---- issue MMA for round r (bank) ----
        if (wid == 0) {
            TCGEN05_FENCE_AFTER();
            if (elect_one()) {
                const uint64_t dA = make_desc(sbase + bank * 32768);
                const uint32_t dst = tmem + bank * 64;
#pragma unroll
                for (int s = 0; s < 8; s++)
                    mma_tf32_ss(dst, dA + offA[s], dBhi + offB[s], IDESC_TF32, s > 0);
#pragma unroll
                for (int s = 0; s < 8; s++)
                    mma_tf32_ss(dst, dA + offA[s], dBlo + offB[s], IDESC_TF32, true);
                TCGEN05_COMMIT(sbase + OFF_MBAR + bank * 8);
            }
        }

        // ---- epilogue for round r-1 (other bank), overlapped with MMA r ----
        if (r > 0) {
            const int pb = (r - 1) & 1;
            MBARRIER_WAIT_PARITY(sbase + OFF_MBAR + pb * 8, ((r - 1) >> 1) & 1);
            TCGEN05_FENCE_AFTER();
            uint32_t tmp[32];
            TCGEN05_LD_32X32B_X32(tmp, tmem + pb * 64 + chb);
            TCGEN05_WAIT_LD();
#pragma unroll
            for (int c = 0; c < 32; c++) {
                float v = __uint_as_float(tmp[c]) + b2v[c];
                ysum[c] += fmaxf(v, 0.0f);
            }
            TCGEN05_FENCE_BEFORE();
        }

        hv = hn; jp = jn;
    }

    // ---- tail epilogue (round 7, bank 1) ----
    {
        MBARRIER_WAIT_PARITY(sbase + OFF_MBAR + 8, (7 >> 1) & 1);
        TCGEN05_FENCE_AFTER();
        uint32_t tmp[32];
        TCGEN05_LD_32X32B_X32(tmp, tmem + 64 + chb);
        TCGEN05_WAIT_LD();
#pragma unroll
        for (int c = 0; c < 32; c++) {
            float v = __uint_as_float(tmp[c]) + b2v[c];
            ysum[c] += fmaxf(v, 0.0f);
        }
        TCGEN05_FENCE_BEFORE();
    }

    // cross-lane reduce over ii (lane l and l^16 share jj) and write partials
    __syncthreads();
    float* sRed = (float*)smem;    // reuse U space: [4 sub][16 jj][64 ch]
    const int sub = wid & 3;
#pragma unroll
    for (int c = 0; c < 32; c++) {
        float v = ysum[c] + __shfl_xor_sync(0xFFFFFFFFu, ysum[c], 16);
        if (lid < 16) sRed[(sub * 16 + lid) * 64 + chb + c] = v;
    }
    __syncthreads();
#pragma unroll
    for (int q = 0; q < 4; q++) {
        int o = t * 4 + q;
        int jj = o >> 6, ch = o & 63;
        float s = sRed[(0 * 16 + jj) * 64 + ch] + sRed[(1 * 16 + jj) * 64 + ch] +
                  sRed[(2 * 16 + jj) * 64 + ch] + sRed[(3 * 16 + jj) * 64 + ch];
        g_ysum_part[(ic * NN + j0 + jj) * 64 + ch] = s;
    }

    __syncthreads();
    if (t == 0) { MBARRIER_INVAL(sbase + OFF_MBAR); MBARRIER_INVAL(sbase + OFF_MBAR + 8); }
    if (wid == 0) TCGEN05_DEALLOC(tmem, 128);

#else  // ---------- scalar fallback (family-PTX pass; never runs on sm_103a) ----------
    float* sW2 = (float*)(smem + OFF_WHI);     // [c][k] linear
    float* sU  = (float*)smem;                 // [k][16]
    float* sHi = (float*)(smem + OFF_FHI);
    float* sJ  = (float*)(smem + OFF_FJ);

#pragma unroll
    for (int q = 0; q < 16; q++) {
        int idx = t + q * 256;
        sW2[idx] = W2[idx];
    }
    if (t < 64) { swJ[t] = W1[t * 35 + 32]; sB2[t] = b2[t]; }
#pragma unroll
    for (int q = 0; q < 4; q++) {
        int idx = t + q * 256;
        sHj[idx] = g_hj[(j0 + (idx >> 6)) * 64 + (idx & 63)];
    }
    __syncthreads();

    const int jj = t >> 4;
    float acc[4] = {0.f, 0.f, 0.f, 0.f};
    for (int i = ic * 64; i < ic * 64 + 64; i++) {
        if (t < 64) sHi[t] = g_hi[i * 64 + t];
        if (t < 16) sJ[t] = J[i * NN + j0 + t];
        __syncthreads();
#pragma unroll
        for (int q = 0; q < 4; q++) {
            int idx = t * 4 + q;
            int k = idx >> 4, jl = idx & 15;
            float u = fmaf(sJ[jl], swJ[k], sHi[k] + sHj[jl * 64 + k]);
            sU[k * 16 + jl] = fmaxf(u, 0.0f);
        }
        __syncthreads();
#pragma unroll
        for (int q = 0; q < 4; q++) {
            int ch = (t & 15) * 4 + q;
            float v = sB2[ch];
            for (int k = 0; k < 64; k++) v = fmaf(sW2[ch * 64 + k], sU[k * 16 + jj], v);
            acc[q] += fmaxf(v, 0.0f);
        }
        __syncthreads();
    }
#pragma unroll
    for (int q = 0; q < 4; q++) {
        int ch = (t & 15) * 4 + q;
        g_ysum_part[(ic * NN + j0 + jj) * 64 + ch] = acc[q];
    }
#endif
}

// ============================================================
// Fused m_j + GRU + next-step hi/hj
// grid 128, block 128 (4 nodes per block)
// ============================================================
__global__ void mj_gru_kernel(const float* __restrict__ W3, const float* __restrict__ b3,
                              const float* __restrict__ W_ih, const float* __restrict__ b_ih,
                              const float* __restrict__ W_hh, const float* __restrict__ b_hh,
                              const float* __restrict__ W1, const float* __restrict__ b1,
                              const float* __restrict__ bn) {
    __shared__ float sY[4][64];
    __shared__ float sH[4][16], sMJ[4][32], sGI[4][48], sGH[4][48], sHn[4][16];
    const int t = threadIdx.x;
    const int n0 = blockIdx.x * 4;

    // reduce 8 partials: 4 nodes x 64 ch
#pragma unroll
    for (int q = 0; q < 2; q++) {
        int idx = t + q * 128;
        int jl = idx >> 6, k = idx & 63;
        float s = 0.0f;
#pragma unroll
        for (int p = 0; p < 8; p++) s += g_ysum_part[(p * NN + n0 + jl) * 64 + k];
        sY[jl][k] = s;
    }
    if (t < 64) { int nl = t >> 4, s = t & 15; sH[nl][s] = g_h[(n0 + nl) * 16 + s]; }
    __syncthreads();

    // m_j: 4 nodes x 32 ch = 128 threads
    {
        const int jl = t >> 5, c2 = t & 31;
        float s = 512.0f * b3[c2];
#pragma unroll
        for (int k = 0; k < 64; k++) s = fmaf(W3[c2 * 64 + k], sY[jl][k], s);
        sMJ[jl][c2] = s;
    }
    __syncthreads();

    // gates: 4 nodes x 48 = 192
#pragma unroll
    for (int q = 0; q < 2; q++) {
        int idx = t + q * 128;
        if (idx < 192) {
            int nl = idx / 48, g = idx % 48;
            float gi = b_ih[g], gh = b_hh[g];
#pragma unroll
            for (int s = 0; s < 16; s++) {
                gi = fmaf(sH[nl][s], W_ih[g * 48 + s], gi);
                gh = fmaf(sH[nl][s], W_hh[g * 16 + s], gh);
            }
#pragma unroll
            for (int m = 0; m < 32; m++) gi = fmaf(sMJ[nl][m], W_ih[g * 48 + 16 + m], gi);
            sGI[nl][g] = gi;
            sGH[nl][g] = gh;
        }
    }
    __syncthreads();

    if (t < 64) {
        int nl = t >> 4, s = t & 15;
        float r = sigmoidf(sGI[nl][s] + sGH[nl][s]);
        float z = sigmoidf(sGI[nl][16 + s] + sGH[nl][16 + s]);
        float nv = tanhf(sGI[nl][32 + s] + r * sGH[nl][32 + s]);
        float hn = (1.0f - z) * nv + z * sH[nl][s];
        sHn[nl][s] = hn;
        g_h[(n0 + nl) * 16 + s] = hn;
    }
    __syncthreads();

    // hi/hj for next step: 4 nodes x 64 c x {hi,hj} = 512 outputs
#pragma unroll
    for (int q = 0; q < 4; q++) {
        int idx = t + q * 128;
        int nl = idx >> 7, rem = idx & 127;
        int c = rem & 63, which = rem >> 6;
        int ng = n0 + nl;
        const float* w = &W1[c * 35 + (which ? 16 : 0)];
        float s = which ? fmaf(bn[ng], W1[c * 35 + 34], b1[c]) : bn[ng] * W1[c * 35 + 33];
#pragma unroll
        for (int sd = 0; sd < 16; sd++) s = fmaf(sHn[nl][sd], w[sd], s);
        if (which) g_hj[ng * 64 + c] = s;
        else       g_hi[ng * 64 + c] = s;
    }
}

// ============================================================
// Readout
// ============================================================
__global__ void readout_kernel(const float* __restrict__ Wr1, const float* __restrict__ br1,
                               const float* __restrict__ Wr2, const float* __restrict__ br2,
                               const float* __restrict__ Wr3, const float* __restrict__ br3,
                               float* __restrict__ out) {
    __shared__ float sH[2][16], sY1[2][64], sY2[2][64], sY3[2][2];
    const int t = threadIdx.x;
    const int n0 = blockIdx.x * 2;

    if (t < 32) sH[t >> 4][t & 15] = g_h[n0 * 16 + t];
    __syncthreads();

    const int nl = t >> 6, o = t & 63;
    float s = br1[o];
#pragma unroll
    for (int k = 0; k < 16; k++) s = fmaf(sH[nl][k], Wr1[o * 16 + k], s);
    sY1[nl][o] = fmaxf(s, 0.0f);
    __syncthreads();

    s = br2[o];
#pragma unroll
    for (int k = 0; k < 64; k++) s = fmaf(sY1[nl][k], Wr2[o * 64 + k], s);
    sY2[nl][o] = fmaxf(s, 0.0f);
    __syncthreads();

    if (o < 2) {
        s = br3[o];
#pragma unroll
        for (int k = 0; k < 64; k++) s = fmaf(sY2[nl][k], Wr3[o * 64 + k], s);
        sY3[nl][o] = sigmoidf(s);
    }
    __syncthreads();
    if (o < 2) {
        out[(n0 + nl) * 2 + o] = sY3[nl][o] / (sY3[nl][0] + sY3[nl][1]);
    }
}

// ============================================================
extern "C" void kernel_launch(void* const* d_in, const int* in_sizes, int n_in,
                              void* d_out, int out_size) {
    const float* J    = (const float*)d_in[0];
    const float* b    = (const float*)d_in[1];
    const float* W1   = (const float*)d_in[2];
    const float* b1   = (const float*)d_in[3];
    const float* W2   = (const float*)d_in[4];
    const float* b2   = (const float*)d_in[5];
    const float* W3   = (const float*)d_in[6];
    const float* b3   = (const float*)d_in[7];
    const float* W_ih = (const float*)d_in[8];
    const float* b_ih = (const float*)d_in[9];
    const float* W_hh = (const float*)d_in[10];
    const float* b_hh = (const float*)d_in[11];
    const float* Wr1  = (const float*)d_in[12];
    const float* br1  = (const float*)d_in[13];
    const float* Wr2  = (const float*)d_in[14];
    const float* br2  = (const float*)d_in[15];
    const float* Wr3  = (const float*)d_in[16];
    const float* br3  = (const float*)d_in[17];
    float* out = (float*)d_out;

    cudaFuncSetAttribute(edge_tc_kernel, cudaFuncAttributeMaxDynamicSharedMemorySize, SMEM_EDGE);

    init_kernel<<<128, 256>>>(b, W1, b1);
    for (int step = 0; step < 5; step++) {
        edge_tc_kernel<<<dim3(32, 8), 256, SMEM_EDGE>>>(J, W1, W2, b2);
        mj_gru_kernel<<<128, 128>>>(W3, b3, W_ih, b_ih, W_hh, b_hh, W1, b1, b);
    }
    readout_kernel<<<256, 128>>>(Wr1, br1, Wr2, br2, Wr3, br3, out);
}